// round 9
// baseline (speedup 1.0000x reference)
#include <cuda_runtime.h>

// MSELoss: out[0] = mean((yhat - y)^2) over 16384*4096 fp32 elements.
// Single-kernel HBM-bound streaming reduction (threadfence-reduction pattern).
//
// Grid sizing history:
//   R5: regs=34 -> 7 CTAs/SM assumed, grid 1184 caused 2-wave imbalance.
//   R8: __launch_bounds__(256,7) retuned ptxas to regs=32 -> SM can hold 8
//       CTAs; occ showed 56/64 warps. This round: pin (256,8), grid=152*8.
// One full resident wave at 100% occupancy; more warps -> more outstanding
// LDG.128 -> better DRAM latency hiding (issue was 9.8%).
//
// Deterministic: partial order fixed, final sum is a fixed loop over
// g_partials[]; only WHICH CTA finishes last varies. Counter self-resets so
// CUDA-graph replays are stateless.

#define NBLOCKS   1216     // 152 SMs * 8 CTAs (one full wave at 32 regs)
#define NTHREADS  256
#define N_ELEMS   67108864LL   // 16384 * 4096
#define N_VEC4    16777216u    // N_ELEMS / 4

__device__ float g_partials[NBLOCKS];
__device__ unsigned g_done_count = 0;

__device__ __forceinline__ float block_reduce(float v) {
    __shared__ float warp_sums[NTHREADS / 32];
    #pragma unroll
    for (int off = 16; off > 0; off >>= 1)
        v += __shfl_down_sync(0xFFFFFFFFu, v, off);
    int lane = threadIdx.x & 31;
    int wid  = threadIdx.x >> 5;
    if (lane == 0) warp_sums[wid] = v;
    __syncthreads();
    if (wid == 0) {
        v = (lane < NTHREADS / 32) ? warp_sums[lane] : 0.0f;
        #pragma unroll
        for (int off = 16; off > 0; off >>= 1)
            v += __shfl_down_sync(0xFFFFFFFFu, v, off);
    }
    return v;  // valid in (wid==0, lane==0)
}

__device__ __forceinline__ float sqdiff4(float4 a, float4 b, float acc) {
    float d0 = a.x - b.x, d1 = a.y - b.y;
    float d2 = a.z - b.z, d3 = a.w - b.w;
    acc = fmaf(d0, d0, acc); acc = fmaf(d1, d1, acc);
    acc = fmaf(d2, d2, acc); acc = fmaf(d3, d3, acc);
    return acc;
}

__global__ __launch_bounds__(NTHREADS, 8) void mse_kernel(
    const float4* __restrict__ yhat,
    const float4* __restrict__ y,
    float* __restrict__ out)
{
    float acc = 0.0f;
    const unsigned stride = NBLOCKS * NTHREADS;
    unsigned i = blockIdx.x * NTHREADS + threadIdx.x;

    // 4-deep unroll: 8 independent LDG.128 batched at loop front (MLP_p1 = 8)
    for (; i + 3u * stride < N_VEC4; i += 4u * stride) {
        float4 a0 = yhat[i];
        float4 b0 = y[i];
        float4 a1 = yhat[i + stride];
        float4 b1 = y[i + stride];
        float4 a2 = yhat[i + 2u * stride];
        float4 b2 = y[i + 2u * stride];
        float4 a3 = yhat[i + 3u * stride];
        float4 b3 = y[i + 3u * stride];
        acc = sqdiff4(a0, b0, acc);
        acc = sqdiff4(a1, b1, acc);
        acc = sqdiff4(a2, b2, acc);
        acc = sqdiff4(a3, b3, acc);
    }
    // tail: remaining stride-chunks
    for (; i < N_VEC4; i += stride) {
        float4 a = yhat[i];
        float4 b = y[i];
        acc = sqdiff4(a, b, acc);
    }

    float bsum = block_reduce(acc);

    __shared__ bool is_last;
    if (threadIdx.x == 0) {
        g_partials[blockIdx.x] = bsum;
        __threadfence();  // partial visible before counter bump
        unsigned prev = atomicAdd(&g_done_count, 1u);
        is_last = (prev == NBLOCKS - 1u);
    }
    __syncthreads();

    if (is_last) {
        // All partials globally visible (each writer fenced before its
        // atomicAdd and we observed the final count). Partials are L2-hot.
        __threadfence();
        float facc = 0.0f;
        for (int p = threadIdx.x; p < NBLOCKS; p += NTHREADS)
            facc += g_partials[p];
        float total = block_reduce(facc);
        if (threadIdx.x == 0) {
            out[0] = total * (1.0f / (float)N_ELEMS);
            g_done_count = 0;  // reset for next graph replay
        }
    }
}

extern "C" void kernel_launch(void* const* d_in, const int* in_sizes, int n_in,
                              void* d_out, int out_size)
{
    const float4* yhat = (const float4*)d_in[0];
    const float4* y    = (const float4*)d_in[1];
    float* out = (float*)d_out;

    mse_kernel<<<NBLOCKS, NTHREADS>>>(yhat, y, out);
}

// round 12
// speedup vs baseline: 1.0148x; 1.0148x over previous
#include <cuda_runtime.h>

// MSELoss: out[0] = mean((yhat - y)^2) over 16384*4096 fp32 elements.
// Single-kernel HBM-bound streaming reduction (threadfence-reduction pattern).
//
// R9 lesson: occ 86.7%->98.5% left BW flat at ~6.56 TB/s -> not
// occupancy-limited; plateau is the LTS/DRAM path ceiling. This round:
// __ldcs (evict-first) streaming loads — data is touched exactly once, so
// bypassing L2 LRU insertion is free and may recover a few % of DRAM
// efficiency. Everything else unchanged (grid=152*8, one full wave).
//
// Deterministic: partial order fixed, final sum is a fixed loop over
// g_partials[]; only WHICH CTA finishes last varies. Counter self-resets so
// CUDA-graph replays are stateless.

#define NBLOCKS   1216     // 152 SMs * 8 CTAs (one full wave at 32 regs)
#define NTHREADS  256
#define N_ELEMS   67108864LL   // 16384 * 4096
#define N_VEC4    16777216u    // N_ELEMS / 4

__device__ float g_partials[NBLOCKS];
__device__ unsigned g_done_count = 0;

__device__ __forceinline__ float block_reduce(float v) {
    __shared__ float warp_sums[NTHREADS / 32];
    #pragma unroll
    for (int off = 16; off > 0; off >>= 1)
        v += __shfl_down_sync(0xFFFFFFFFu, v, off);
    int lane = threadIdx.x & 31;
    int wid  = threadIdx.x >> 5;
    if (lane == 0) warp_sums[wid] = v;
    __syncthreads();
    if (wid == 0) {
        v = (lane < NTHREADS / 32) ? warp_sums[lane] : 0.0f;
        #pragma unroll
        for (int off = 16; off > 0; off >>= 1)
            v += __shfl_down_sync(0xFFFFFFFFu, v, off);
    }
    return v;  // valid in (wid==0, lane==0)
}

__device__ __forceinline__ float sqdiff4(float4 a, float4 b, float acc) {
    float d0 = a.x - b.x, d1 = a.y - b.y;
    float d2 = a.z - b.z, d3 = a.w - b.w;
    acc = fmaf(d0, d0, acc); acc = fmaf(d1, d1, acc);
    acc = fmaf(d2, d2, acc); acc = fmaf(d3, d3, acc);
    return acc;
}

__global__ __launch_bounds__(NTHREADS, 8) void mse_kernel(
    const float4* __restrict__ yhat,
    const float4* __restrict__ y,
    float* __restrict__ out)
{
    float acc = 0.0f;
    const unsigned stride = NBLOCKS * NTHREADS;
    unsigned i = blockIdx.x * NTHREADS + threadIdx.x;

    // 4-deep unroll: 8 independent streaming LDG.128 batched at loop front
    for (; i + 3u * stride < N_VEC4; i += 4u * stride) {
        float4 a0 = __ldcs(&yhat[i]);
        float4 b0 = __ldcs(&y[i]);
        float4 a1 = __ldcs(&yhat[i + stride]);
        float4 b1 = __ldcs(&y[i + stride]);
        float4 a2 = __ldcs(&yhat[i + 2u * stride]);
        float4 b2 = __ldcs(&y[i + 2u * stride]);
        float4 a3 = __ldcs(&yhat[i + 3u * stride]);
        float4 b3 = __ldcs(&y[i + 3u * stride]);
        acc = sqdiff4(a0, b0, acc);
        acc = sqdiff4(a1, b1, acc);
        acc = sqdiff4(a2, b2, acc);
        acc = sqdiff4(a3, b3, acc);
    }
    // tail: remaining stride-chunks
    for (; i < N_VEC4; i += stride) {
        float4 a = __ldcs(&yhat[i]);
        float4 b = __ldcs(&y[i]);
        acc = sqdiff4(a, b, acc);
    }

    float bsum = block_reduce(acc);

    __shared__ bool is_last;
    if (threadIdx.x == 0) {
        g_partials[blockIdx.x] = bsum;
        __threadfence();  // partial visible before counter bump
        unsigned prev = atomicAdd(&g_done_count, 1u);
        is_last = (prev == NBLOCKS - 1u);
    }
    __syncthreads();

    if (is_last) {
        // All partials globally visible (each writer fenced before its
        // atomicAdd and we observed the final count). Partials are L2-hot.
        __threadfence();
        float facc = 0.0f;
        for (int p = threadIdx.x; p < NBLOCKS; p += NTHREADS)
            facc += g_partials[p];
        float total = block_reduce(facc);
        if (threadIdx.x == 0) {
            out[0] = total * (1.0f / (float)N_ELEMS);
            g_done_count = 0;  // reset for next graph replay
        }
    }
}

extern "C" void kernel_launch(void* const* d_in, const int* in_sizes, int n_in,
                              void* d_out, int out_size)
{
    const float4* yhat = (const float4*)d_in[0];
    const float4* y    = (const float4*)d_in[1];
    float* out = (float*)d_out;

    mse_kernel<<<NBLOCKS, NTHREADS>>>(yhat, y, out);
}